// round 2
// baseline (speedup 1.0000x reference)
#include <cuda_runtime.h>
#include <cstdint>

// mean_aggregator: out[b,:] = (1/32) * sum_s emb[neighbors[b,s], :]
// B=50000, S=32, D=128, emb = 500000x128 fp32 (256 MB > 126 MB L2).
//
// L2-blocked gather: node-id space split into 16 bins of 32768 ids (32 MB of
// table per bin). Each warp owns R=8 rows; accumulators + neighbor ids live in
// registers across the whole bin sweep. All warps sweep bins in the same order
// so the instantaneous table working set fits in L2, converting capacity
// misses into hits. Each neighbor is shfl'd + gathered exactly once.

#define ROWS_PER_WARP 8
#define NUM_BINS 16
#define BIN_SHIFT 15          // bins of 32768 ids; 16*32768 = 524288 >= 500000
#define THREADS 256
#define WARPS_PER_BLOCK (THREADS / 32)

__global__ __launch_bounds__(THREADS, 4)
void mean_agg_binned(const int* __restrict__ neighbors,
                     const float4* __restrict__ emb,   // [N, 32] float4
                     float4* __restrict__ out,         // [B, 32] float4
                     int batch)
{
    const int warp_g = (blockIdx.x * blockDim.x + threadIdx.x) >> 5;
    const int lane   = threadIdx.x & 31;
    const int row0   = warp_g * ROWS_PER_WARP;

    // Load this warp's neighbor ids: lane holds id (row r, sample=lane).
    int ids[ROWS_PER_WARP];
    #pragma unroll
    for (int r = 0; r < ROWS_PER_WARP; ++r) {
        const int row = row0 + r;
        // Sentinel for out-of-range rows: bin = INT_MAX>>15 never matches k<16.
        ids[r] = (row < batch) ? neighbors[row * 32 + lane] : 0x7fffffff;
    }

    float4 acc[ROWS_PER_WARP];
    #pragma unroll
    for (int r = 0; r < ROWS_PER_WARP; ++r)
        acc[r] = make_float4(0.f, 0.f, 0.f, 0.f);

    for (int k = 0; k < NUM_BINS; ++k) {
        #pragma unroll
        for (int r = 0; r < ROWS_PER_WARP; ++r) {
            unsigned mask =
                __ballot_sync(0xffffffffu, (ids[r] >> BIN_SHIFT) == k);
            while (mask) {
                const int src = __ffs(mask) - 1;
                mask &= mask - 1;
                const int n = __shfl_sync(0xffffffffu, ids[r], src);
                const float4 v = __ldg(&emb[(size_t)n * 32 + lane]);
                acc[r].x += v.x;
                acc[r].y += v.y;
                acc[r].z += v.z;
                acc[r].w += v.w;
            }
        }
        // Keep the block's warps on the same bin (loose global lockstep).
        __syncthreads();
    }

    const float inv = 1.0f / 32.0f;
    #pragma unroll
    for (int r = 0; r < ROWS_PER_WARP; ++r) {
        const int row = row0 + r;
        if (row < batch) {
            float4 a = acc[r];
            a.x *= inv; a.y *= inv; a.z *= inv; a.w *= inv;
            out[(size_t)row * 32 + lane] = a;
        }
    }
}

extern "C" void kernel_launch(void* const* d_in, const int* in_sizes, int n_in,
                              void* d_out, int out_size)
{
    const int* neighbors = (const int*)d_in[0];     // [B, 32] int32
    const float4* emb    = (const float4*)d_in[1];  // [N, 128] fp32 as float4

    const int batch = in_sizes[0] / 32;             // 50000

    const int rows_per_block = WARPS_PER_BLOCK * ROWS_PER_WARP;  // 64
    const int blocks = (batch + rows_per_block - 1) / rows_per_block;

    mean_agg_binned<<<blocks, THREADS>>>(neighbors, emb, (float4*)d_out, batch);
}

// round 3
// speedup vs baseline: 2.2080x; 2.2080x over previous
#include <cuda_runtime.h>
#include <cstdint>

// mean_aggregator: out[b,:] = (1/32) * sum_s emb[neighbors[b,s], :]
// B=50000, S=32, D=128, emb 500000x128 fp32 (256 MB > 126 MB L2).
//
// Two-phase:
//  1) warp-bitonic sort each row's 32 neighbor ids (ascending) into scratch.
//  2) R1-style max-MLP gather, but warp owns 8 rows and walks sorted position
//     s outermost -> all warps sweep the id space front-to-back together,
//     giving a sliding L2-resident window (statistical lockstep) while every
//     load stays fully unrolled and independent.

#define ROWS_PER_WARP 8
#define THREADS 256
#define WARPS_PER_BLOCK (THREADS / 32)

__device__ int g_sorted[1600000];   // 50000 * 32 ids, 6.4 MB scratch

__global__ __launch_bounds__(THREADS)
void sort_rows_kernel(const int* __restrict__ neighbors, int batch)
{
    const int warp = (blockIdx.x * blockDim.x + threadIdx.x) >> 5;
    const int lane = threadIdx.x & 31;
    if (warp >= batch) return;

    int v = neighbors[warp * 32 + lane];

    // 32-element bitonic sort across the warp (ascending).
    #pragma unroll
    for (int k = 2; k <= 32; k <<= 1) {
        #pragma unroll
        for (int j = k >> 1; j > 0; j >>= 1) {
            const int other   = __shfl_xor_sync(0xffffffffu, v, j);
            const bool up     = ((lane & k) == 0);
            const bool lower  = ((lane & j) == 0);   // lane < partner
            v = ((lower == up) ? min(v, other) : max(v, other));
        }
    }

    g_sorted[warp * 32 + lane] = v;
}

__global__ __launch_bounds__(THREADS, 4)   // cap 64 regs -> 4 blocks/SM, ~1.3 waves
void mean_agg_sorted(const float4* __restrict__ emb,   // [N, 32] float4
                     float4* __restrict__ out,         // [B, 32] float4
                     int batch)
{
    const int warp_g = (blockIdx.x * blockDim.x + threadIdx.x) >> 5;
    const int lane   = threadIdx.x & 31;
    const int row0   = warp_g * ROWS_PER_WARP;

    // Lane l holds sorted id at position l for each of this warp's rows.
    int ids[ROWS_PER_WARP];
    #pragma unroll
    for (int r = 0; r < ROWS_PER_WARP; ++r) {
        const int row = row0 + r;
        ids[r] = (row < batch) ? g_sorted[row * 32 + lane] : 0;
    }

    float4 acc[ROWS_PER_WARP];
    #pragma unroll
    for (int r = 0; r < ROWS_PER_WARP; ++r)
        acc[r] = make_float4(0.f, 0.f, 0.f, 0.f);

    // s outermost: all rows (and all warps) advance through the sorted id
    // space together. 256 fully unrolled independent loads, 8 acc chains.
    #pragma unroll
    for (int s = 0; s < 32; ++s) {
        #pragma unroll
        for (int r = 0; r < ROWS_PER_WARP; ++r) {
            const int n = __shfl_sync(0xffffffffu, ids[r], s);
            const float4 v = __ldg(&emb[(size_t)n * 32 + lane]);
            acc[r].x += v.x;
            acc[r].y += v.y;
            acc[r].z += v.z;
            acc[r].w += v.w;
        }
    }

    const float inv = 1.0f / 32.0f;
    #pragma unroll
    for (int r = 0; r < ROWS_PER_WARP; ++r) {
        const int row = row0 + r;
        if (row < batch) {
            float4 a = acc[r];
            a.x *= inv; a.y *= inv; a.z *= inv; a.w *= inv;
            out[(size_t)row * 32 + lane] = a;
        }
    }
}

extern "C" void kernel_launch(void* const* d_in, const int* in_sizes, int n_in,
                              void* d_out, int out_size)
{
    const int* neighbors = (const int*)d_in[0];     // [B, 32] int32
    const float4* emb    = (const float4*)d_in[1];  // [N, 128] fp32 as float4

    const int batch = in_sizes[0] / 32;             // 50000

    // Phase 1: sort each row's neighbor ids.
    {
        const int warps_needed = batch;
        const int blocks = (warps_needed + WARPS_PER_BLOCK - 1) / WARPS_PER_BLOCK;
        sort_rows_kernel<<<blocks, THREADS>>>(neighbors, batch);
    }

    // Phase 2: lockstep sorted gather.
    {
        const int rows_per_block = WARPS_PER_BLOCK * ROWS_PER_WARP;   // 64
        const int blocks = (batch + rows_per_block - 1) / rows_per_block;
        mean_agg_sorted<<<blocks, THREADS>>>(emb, (float4*)d_out, batch);
    }
}

// round 4
// speedup vs baseline: 2.7502x; 1.2456x over previous
#include <cuda_runtime.h>
#include <cstdint>

// mean_aggregator: out[b,:] = (1/32) * sum_s emb[neighbors[b,s], :]
// B=50000, S=32, D=128, emb 500000x128 fp32 (256 MB > 126 MB L2).
//
// Fixed-window multi-pass gather: 3 launches, pass p gathers only ids in
// [lo_p, hi_p) (~85 MB table slice, L2-resident for the whole launch).
// Loads stay fully unrolled + predicated (no ballot serialization), so each
// warp keeps up to 32 independent loads in flight. Output partial sums RMW
// through L2 between passes (L2 persists across launches).

#define THREADS 256
#define WARPS_PER_BLOCK (THREADS / 32)
#define NPASS 3

__global__ __launch_bounds__(THREADS)
void mean_agg_pass(const int* __restrict__ neighbors,
                   const float4* __restrict__ emb,   // [N, 32] float4
                   float4* __restrict__ out,         // [B, 32] float4
                   int batch, int lo, int hi, int pass)
{
    const int warp = (blockIdx.x * blockDim.x + threadIdx.x) >> 5;
    const int lane = threadIdx.x & 31;
    if (warp >= batch) return;

    // Coalesced: lane s holds neighbor id s of this row.
    const int my_nbr = neighbors[warp * 32 + lane];

    float4 acc;
    if (pass == 0) {
        acc = make_float4(0.f, 0.f, 0.f, 0.f);
    } else {
        acc = out[(size_t)warp * 32 + lane];   // L2-resident partial
    }

    #pragma unroll
    for (int s = 0; s < 32; ++s) {
        const int n = __shfl_sync(0xffffffffu, my_nbr, s);
        if (n >= lo && n < hi) {               // predicated LDG + FADD
            const float4 v = __ldg(&emb[(size_t)n * 32 + lane]);
            acc.x += v.x;
            acc.y += v.y;
            acc.z += v.z;
            acc.w += v.w;
        }
    }

    if (pass == NPASS - 1) {
        const float inv = 1.0f / 32.0f;
        acc.x *= inv; acc.y *= inv; acc.z *= inv; acc.w *= inv;
    }

    out[(size_t)warp * 32 + lane] = acc;
}

extern "C" void kernel_launch(void* const* d_in, const int* in_sizes, int n_in,
                              void* d_out, int out_size)
{
    const int* neighbors = (const int*)d_in[0];     // [B, 32] int32
    const float4* emb    = (const float4*)d_in[1];  // [N, 128] fp32 as float4

    const int batch     = in_sizes[0] / 32;         // 50000
    const int num_nodes = in_sizes[1] / 128;        // 500000

    const int blocks = (batch + WARPS_PER_BLOCK - 1) / WARPS_PER_BLOCK;

    for (int p = 0; p < NPASS; ++p) {
        const int lo = (int)(((long long)num_nodes * p) / NPASS);
        const int hi = (p == NPASS - 1)
                         ? num_nodes
                         : (int)(((long long)num_nodes * (p + 1)) / NPASS);
        mean_agg_pass<<<blocks, THREADS>>>(neighbors, emb, (float4*)d_out,
                                           batch, lo, hi, p);
    }
}